// round 5
// baseline (speedup 1.0000x reference)
#include <cuda_runtime.h>
#include <math.h>

#define B_  2
#define C_  384
#define HW  1024
#define NHEAD 12
#define NGROUP 6
#define HC  32
#define GC  64
#define NS  1024
#define SCALE 0.17677669529663687f   // 1/sqrt(32)

// ---------------- scratch ----------------------------------------------------
__device__ float g_q  [B_ * C_ * HW];
__device__ float g_pos[B_ * NGROUP * NS * 2];
__device__ float g_xs [B_ * NGROUP * GC * NS];
__device__ float g_k  [B_ * C_ * NS];
__device__ float g_v  [B_ * C_ * NS];
__device__ float g_o  [B_ * C_ * HW];

// ---------------- tf32 tensor-core GEMM --------------------------------------
// Y[o,p] = sum_c W[o,c] X[c,p] + bias[o];  M=384(o), N=1024(p), K=384(c)
// block tile 64(M) x 128(N), BK=16, 128 threads (4 warps, 2x2), warp tile 32x64

#define BM 64
#define BN 128
#define BK 16
#define APAD 20
#define BPAD 136

__device__ __forceinline__ unsigned f2tf32(float f) {
    unsigned r;
    asm("cvt.rna.tf32.f32 %0, %1;" : "=r"(r) : "f"(f));
    return r;
}

__device__ __forceinline__ void mma_tf32(float d[4], const unsigned a[4], unsigned b0, unsigned b1) {
    asm volatile(
        "mma.sync.aligned.m16n8k8.row.col.f32.tf32.tf32.f32 "
        "{%0,%1,%2,%3}, {%4,%5,%6,%7}, {%8,%9}, {%0,%1,%2,%3};"
        : "+f"(d[0]), "+f"(d[1]), "+f"(d[2]), "+f"(d[3])
        : "r"(a[0]), "r"(a[1]), "r"(a[2]), "r"(a[3]), "r"(b0), "r"(b1));
}

__device__ __forceinline__ void mma_gemm_core(
        float* __restrict__ Yb, const float* __restrict__ W,
        const float* __restrict__ bias, const float* __restrict__ Xb,
        int o0, int p0) {
    __shared__ unsigned As[2][BM][APAD];
    __shared__ unsigned Bs[2][BK][BPAD];

    int tid = threadIdx.x;
    int lane = tid & 31, warp = tid >> 5;
    int wm = warp & 1, wn = warp >> 1;       // 2 x 2 warps
    int qr = lane >> 2, qc = lane & 3;

    float d[2][8][4];
    #pragma unroll
    for (int mt = 0; mt < 2; mt++)
        #pragma unroll
        for (int nt = 0; nt < 8; nt++)
            #pragma unroll
            for (int r = 0; r < 4; r++) d[mt][nt][r] = 0.f;

    float4 ra[2], rb[4];

    int a_row0 = tid >> 2,          a_c4_0 = tid & 3;
    int a_row1 = (tid + 128) >> 2,  a_c4_1 = tid & 3;
    int b_row[4], b_c4[4];
    #pragma unroll
    for (int j = 0; j < 4; j++) { int idx = tid + j * 128; b_row[j] = idx >> 5; b_c4[j] = idx & 31; }

    #define LDG_TILE(k0)                                                                  \
        ra[0] = *(const float4*)&W[(size_t)(o0 + a_row0) * C_ + (k0) + a_c4_0 * 4];       \
        ra[1] = *(const float4*)&W[(size_t)(o0 + a_row1) * C_ + (k0) + a_c4_1 * 4];       \
        _Pragma("unroll")                                                                 \
        for (int j = 0; j < 4; j++)                                                       \
            rb[j] = *(const float4*)&Xb[(size_t)((k0) + b_row[j]) * HW + p0 + b_c4[j] * 4];

    #define STS_TILE(buf)                                                                 \
        As[buf][a_row0][a_c4_0 * 4 + 0] = f2tf32(ra[0].x);                                \
        As[buf][a_row0][a_c4_0 * 4 + 1] = f2tf32(ra[0].y);                                \
        As[buf][a_row0][a_c4_0 * 4 + 2] = f2tf32(ra[0].z);                                \
        As[buf][a_row0][a_c4_0 * 4 + 3] = f2tf32(ra[0].w);                                \
        As[buf][a_row1][a_c4_1 * 4 + 0] = f2tf32(ra[1].x);                                \
        As[buf][a_row1][a_c4_1 * 4 + 1] = f2tf32(ra[1].y);                                \
        As[buf][a_row1][a_c4_1 * 4 + 2] = f2tf32(ra[1].z);                                \
        As[buf][a_row1][a_c4_1 * 4 + 3] = f2tf32(ra[1].w);                                \
        _Pragma("unroll")                                                                 \
        for (int j = 0; j < 4; j++) {                                                     \
            Bs[buf][b_row[j]][b_c4[j] * 4 + 0] = f2tf32(rb[j].x);                         \
            Bs[buf][b_row[j]][b_c4[j] * 4 + 1] = f2tf32(rb[j].y);                         \
            Bs[buf][b_row[j]][b_c4[j] * 4 + 2] = f2tf32(rb[j].z);                         \
            Bs[buf][b_row[j]][b_c4[j] * 4 + 3] = f2tf32(rb[j].w);                         \
        }

    LDG_TILE(0);
    STS_TILE(0);
    __syncthreads();

    const int NIT = C_ / BK;   // 24
    for (int it = 0; it < NIT; it++) {
        int cur = it & 1;
        if (it < NIT - 1) { LDG_TILE((it + 1) * BK); }
        #pragma unroll
        for (int ks = 0; ks < 2; ks++) {
            int kb = ks * 8;
            unsigned af[2][4];
            #pragma unroll
            for (int mt = 0; mt < 2; mt++) {
                int rbse = wm * 32 + mt * 16;
                af[mt][0] = As[cur][rbse + qr    ][kb + qc    ];
                af[mt][1] = As[cur][rbse + qr + 8][kb + qc    ];
                af[mt][2] = As[cur][rbse + qr    ][kb + qc + 4];
                af[mt][3] = As[cur][rbse + qr + 8][kb + qc + 4];
            }
            #pragma unroll
            for (int nt = 0; nt < 8; nt++) {
                int nb = wn * 64 + nt * 8 + qr;
                unsigned b0 = Bs[cur][kb + qc    ][nb];
                unsigned b1 = Bs[cur][kb + qc + 4][nb];
                mma_tf32(d[0][nt], af[0], b0, b1);
                mma_tf32(d[1][nt], af[1], b0, b1);
            }
        }
        if (it < NIT - 1) { STS_TILE(cur ^ 1); }
        __syncthreads();
    }

    #pragma unroll
    for (int mt = 0; mt < 2; mt++) {
        int ob = o0 + wm * 32 + mt * 16 + qr;
        float bv0 = bias[ob], bv1 = bias[ob + 8];
        #pragma unroll
        for (int nt = 0; nt < 8; nt++) {
            int p = p0 + wn * 64 + nt * 8 + 2 * qc;
            *(float2*)&Yb[(size_t)ob * HW + p] =
                make_float2(d[mt][nt][0] + bv0, d[mt][nt][1] + bv0);
            *(float2*)&Yb[(size_t)(ob + 8) * HW + p] =
                make_float2(d[mt][nt][2] + bv1, d[mt][nt][3] + bv1);
        }
    }
    #undef LDG_TILE
    #undef STS_TILE
}

__global__ __launch_bounds__(128) void mma_gemm_kernel(
        float* __restrict__ Y, const float* __restrict__ W,
        const float* __restrict__ X, const float* __restrict__ bias) {
    int b = blockIdx.z;
    mma_gemm_core(Y + (size_t)b * C_ * HW, W, bias, X + (size_t)b * C_ * HW,
                  blockIdx.y * BM, blockIdx.x * BN);
}

__global__ __launch_bounds__(128) void mma_gemm_kv_kernel(
        float* __restrict__ K, const float* __restrict__ Wk, const float* __restrict__ bk,
        float* __restrict__ V, const float* __restrict__ Wv, const float* __restrict__ bv,
        const float* __restrict__ X) {
    int b = blockIdx.z;
    int yy = blockIdx.y;
    const float* W  = (yy < 6) ? Wk : Wv;
    const float* bb = (yy < 6) ? bk : bv;
    float* Y        = (yy < 6) ? K  : V;
    mma_gemm_core(Y + (size_t)b * C_ * NS, W, bb, X + (size_t)b * C_ * NS,
                  (yy % 6) * BM, blockIdx.x * BN);
}

// ---------------- offset branch ----------------------------------------------
__global__ void offset_kernel(const float* __restrict__ q,
                              const float* __restrict__ dw_w, const float* __restrict__ dw_b,
                              const float* __restrict__ ln_g, const float* __restrict__ ln_b,
                              const float* __restrict__ pw_w, float* __restrict__ pos) {
    int c = threadIdx.x;        // 0..63
    int p = threadIdx.y;        // 0..3
    int bs = blockIdx.x * 4 + p;
    int bg = bs >> 10;
    int s  = bs & 1023;
    int y = s >> 5, x = s & 31;
    int b = bg / NGROUP, g = bg % NGROUP;
    const float* qc = q + ((size_t)b * C_ + g * GC + c) * HW;
    const float* w  = dw_w + c * 49;
    float acc = dw_b[c];
    #pragma unroll
    for (int dy = 0; dy < 7; dy++) {
        int yy = y + dy - 3;
        if (yy < 0 || yy > 31) continue;
        #pragma unroll
        for (int dx = 0; dx < 7; dx++) {
            int xx = x + dx - 3;
            if (xx < 0 || xx > 31) continue;
            acc += w[dy * 7 + dx] * qc[yy * 32 + xx];
        }
    }
    __shared__ float ra[4][2], rb[4][2], rc[4][2], rd[4][2];
    int half = c >> 5;
    float v = acc;
    #pragma unroll
    for (int o = 16; o; o >>= 1) v += __shfl_down_sync(0xffffffffu, v, o);
    if ((c & 31) == 0) ra[p][half] = v;
    __syncthreads();
    float mu = (ra[p][0] + ra[p][1]) * (1.f / 64.f);
    float d = acc - mu;
    float v2 = d * d;
    #pragma unroll
    for (int o = 16; o; o >>= 1) v2 += __shfl_down_sync(0xffffffffu, v2, o);
    if ((c & 31) == 0) rb[p][half] = v2;
    __syncthreads();
    float var = (rb[p][0] + rb[p][1]) * (1.f / 64.f);
    float on = d * rsqrtf(var + 1e-5f) * ln_g[c] + ln_b[c];
    float ge = 0.5f * on * (1.f + erff(on * 0.70710678118654752f));
    float p0 = ge * pw_w[c];
    float p1 = ge * pw_w[GC + c];
    #pragma unroll
    for (int o = 16; o; o >>= 1) {
        p0 += __shfl_down_sync(0xffffffffu, p0, o);
        p1 += __shfl_down_sync(0xffffffffu, p1, o);
    }
    if ((c & 31) == 0) { rc[p][half] = p0; rd[p][half] = p1; }
    __syncthreads();
    if (c == 0) {
        float off_y = tanhf(rc[p][0] + rc[p][1]) * (2.0f / 32.0f);
        float off_x = tanhf(rd[p][0] + rd[p][1]) * (2.0f / 32.0f);
        float ry = ((float)y + 0.5f) * (1.f / 16.f) - 1.f;
        float rx = ((float)x + 0.5f) * (1.f / 16.f) - 1.f;
        pos[(bg * NS + s) * 2 + 0] = off_y + ry;
        pos[(bg * NS + s) * 2 + 1] = off_x + rx;
    }
}

// ---------------- grid sample -> xs ------------------------------------------
__global__ void sample_kernel(const float* __restrict__ x, const float* __restrict__ pos,
                              float* __restrict__ xs) {
    int idx = blockIdx.x * blockDim.x + threadIdx.x;
    if (idx >= B_ * NGROUP * GC * NS) return;
    int s  = idx & 1023;
    int c  = (idx >> 10) & 63;
    int bg = idx >> 16;
    int b = bg / NGROUP, g = bg % NGROUP;
    float py = pos[(bg * NS + s) * 2 + 0];
    float px = pos[(bg * NS + s) * 2 + 1];
    float gx = (px + 1.f) * 0.5f * 31.f;
    float gy = (py + 1.f) * 0.5f * 31.f;
    float x0f = floorf(gx), y0f = floorf(gy);
    float wx = gx - x0f, wy = gy - y0f;
    int x0 = (int)x0f, y0 = (int)y0f;
    const float* img = x + ((size_t)b * C_ + g * GC + c) * HW;
    float acc = 0.f;
    bool x0v = (unsigned)x0 < 32u, x1v = (unsigned)(x0 + 1) < 32u;
    bool y0v = (unsigned)y0 < 32u, y1v = (unsigned)(y0 + 1) < 32u;
    if (x0v && y0v) acc += (1.f - wx) * (1.f - wy) * img[y0 * 32 + x0];
    if (x1v && y0v) acc += wx * (1.f - wy)         * img[y0 * 32 + x0 + 1];
    if (x0v && y1v) acc += (1.f - wx) * wy         * img[(y0 + 1) * 32 + x0];
    if (x1v && y1v) acc += wx * wy                 * img[(y0 + 1) * 32 + x0 + 1];
    xs[idx] = acc;
}

// ---------------- flash-style fused attention --------------------------------
__device__ __forceinline__ float bilin63(const float* __restrict__ tab, float gy, float gx) {
    float x0f = floorf(gx), y0f = floorf(gy);
    float wx = gx - x0f, wy = gy - y0f;
    int x0 = (int)x0f, y0 = (int)y0f;
    bool x0v = (unsigned)x0 < 63u, x1v = (unsigned)(x0 + 1) < 63u;
    bool y0v = (unsigned)y0 < 63u, y1v = (unsigned)(y0 + 1) < 63u;
    float r = 0.f;
    if (x0v && y0v) r += (1.f - wx) * (1.f - wy) * tab[y0 * 63 + x0];
    if (x1v && y0v) r += wx * (1.f - wy)         * tab[y0 * 63 + x0 + 1];
    if (x0v && y1v) r += (1.f - wx) * wy         * tab[(y0 + 1) * 63 + x0];
    if (x1v && y1v) r += wx * wy                 * tab[(y0 + 1) * 63 + x0 + 1];
    return r;
}

__global__ __launch_bounds__(256) void attn2_kernel(
        const float* __restrict__ q, const float* __restrict__ k,
        const float* __restrict__ v, const float* __restrict__ pos,
        const float* __restrict__ rpe, float* __restrict__ out) {
    __shared__ float Qs[32][64];
    __shared__ float Ks[32][64];
    __shared__ float Vs[32][68];
    __shared__ float Ps[64][68];
    __shared__ float posy[64], posx[64];

    int bh = blockIdx.y;
    int b = bh / NHEAD, h = bh % NHEAD;
    int bg = b * NGROUP + (h >> 1);
    int m0 = blockIdx.x * 64;
    int tid = threadIdx.x;
    int tx = tid & 15, ty = tid >> 4;

    const float* qb = q + ((size_t)b * C_ + h * HC) * HW;
    const float* kb = k + ((size_t)b * C_ + h * HC) * NS;
    const float* vb = v + ((size_t)b * C_ + h * HC) * NS;
    const float* tab = rpe + h * 63 * 63;

    #pragma unroll
    for (int i = tid; i < HC * 64; i += 256) {
        int c = i >> 6, m = i & 63;
        Qs[c][m] = qb[(size_t)c * HW + m0 + m];
    }

    float qy[4], qx[4];
    #pragma unroll
    for (int i = 0; i < 4; i++) {
        int mg = m0 + ty * 4 + i;
        qy[i] = ((float)(mg >> 5) + 0.5f) * (1.f / 16.f) - 1.f;
        qx[i] = ((float)(mg & 31) + 0.5f) * (1.f / 16.f) - 1.f;
    }

    float mrow[4] = {-1e30f, -1e30f, -1e30f, -1e30f};
    float lrow[4] = {};
    float O[4][2] = {};

    for (int n0 = 0; n0 < NS; n0 += 64) {
        __syncthreads();
        #pragma unroll
        for (int i = tid; i < HC * 64; i += 256) {
            int c = i >> 6, n = i & 63;
            Ks[c][n] = kb[(size_t)c * NS + n0 + n];
            Vs[c][n] = vb[(size_t)c * NS + n0 + n];
        }
        if (tid < 64) {
            posy[tid] = pos[(bg * NS + n0 + tid) * 2 + 0];
            posx[tid] = pos[(bg * NS + n0 + tid) * 2 + 1];
        }
        __syncthreads();

        float s[4][4] = {};
        #pragma unroll
        for (int kk = 0; kk < HC; kk++) {
            float4 xv = *(const float4*)&Ks[kk][tx * 4];
            float4 wv = *(const float4*)&Qs[kk][ty * 4];
            s[0][0] += wv.x * xv.x; s[0][1] += wv.x * xv.y; s[0][2] += wv.x * xv.z; s[0][3] += wv.x * xv.w;
            s[1][0] += wv.y * xv.x; s[1][1] += wv.y * xv.y; s[1][2] += wv.y * xv.z; s[1][3] += wv.y * xv.w;
            s[2][0] += wv.z * xv.x; s[2][1] += wv.z * xv.y; s[2][2] += wv.z * xv.z; s[2][3] += wv.z * xv.w;
            s[3][0] += wv.w * xv.x; s[3][1] += wv.w * xv.y; s[3][2] += wv.w * xv.z; s[3][3] += wv.w * xv.w;
        }
        #pragma unroll
        for (int j = 0; j < 4; j++) {
            float py = posy[tx * 4 + j];
            float px = posx[tx * 4 + j];
            #pragma unroll
            for (int i = 0; i < 4; i++) {
                float gy = ((qy[i] - py) * 0.5f + 1.f) * 31.f;
                float gx = ((qx[i] - px) * 0.5f + 1.f) * 31.f;
                s[i][j] = s[i][j] * SCALE + bilin63(tab, gy, gx);
            }
        }
        #pragma unroll
        for (int i = 0; i < 4; i++) {
            float tmax = fmaxf(fmaxf(s[i][0], s[i][1]), fmaxf(s[i][2], s[i][3]));
            #pragma unroll
            for (int o = 8; o; o >>= 1) tmax = fmaxf(tmax, __shfl_xor_sync(0xffffffffu, tmax, o));
            float mnew = fmaxf(mrow[i], tmax);
            float alpha = __expf(mrow[i] - mnew);
            mrow[i] = mnew;
            float e0 = __expf(s[i][0] - mnew);
            float e1 = __expf(s[i][1] - mnew);
            float e2 = __expf(s[i][2] - mnew);
            float e3 = __expf(s[i][3] - mnew);
            float4 ev = make_float4(e0, e1, e2, e3);
            *(float4*)&Ps[ty * 4 + i][tx * 4] = ev;
            float rs = e0 + e1 + e2 + e3;
            #pragma unroll
            for (int o = 8; o; o >>= 1) rs += __shfl_xor_sync(0xffffffffu, rs, o);
            lrow[i] = lrow[i] * alpha + rs;
            O[i][0] *= alpha;
            O[i][1] *= alpha;
        }
        __syncthreads();
        #pragma unroll
        for (int nn = 0; nn < 64; nn += 4) {
            float4 v0 = *(const float4*)&Vs[tx][nn];
            float4 v1 = *(const float4*)&Vs[tx + 16][nn];
            #pragma unroll
            for (int i = 0; i < 4; i++) {
                float4 pp = *(const float4*)&Ps[ty * 4 + i][nn];
                O[i][0] += pp.x * v0.x + pp.y * v0.y + pp.z * v0.z + pp.w * v0.w;
                O[i][1] += pp.x * v1.x + pp.y * v1.y + pp.z * v1.z + pp.w * v1.w;
            }
        }
    }

    float* ob = out + ((size_t)b * C_ + h * HC) * HW;
    #pragma unroll
    for (int i = 0; i < 4; i++) {
        float inv = 1.f / lrow[i];
        int m = m0 + ty * 4 + i;
        ob[(size_t)tx * HW + m]        = O[i][0] * inv;
        ob[(size_t)(tx + 16) * HW + m] = O[i][1] * inv;
    }
}

// ---------------- launch -----------------------------------------------------
extern "C" void kernel_launch(void* const* d_in, const int* in_sizes, int n_in,
                              void* d_out, int out_size) {
    const float* x      = (const float*)d_in[0];
    const float* Wq     = (const float*)d_in[1];
    const float* bq     = (const float*)d_in[2];
    const float* Wk     = (const float*)d_in[3];
    const float* bk     = (const float*)d_in[4];
    const float* Wv     = (const float*)d_in[5];
    const float* bv     = (const float*)d_in[6];
    const float* Wo     = (const float*)d_in[7];
    const float* bo     = (const float*)d_in[8];
    const float* dw_w   = (const float*)d_in[9];
    const float* dw_b   = (const float*)d_in[10];
    const float* ln_g   = (const float*)d_in[11];
    const float* ln_b   = (const float*)d_in[12];
    const float* pw_w   = (const float*)d_in[13];
    const float* rpe    = (const float*)d_in[14];
    float* y = (float*)d_out;

    float *q, *pos, *xs, *k, *v, *o;
    cudaGetSymbolAddress((void**)&q,   g_q);
    cudaGetSymbolAddress((void**)&pos, g_pos);
    cudaGetSymbolAddress((void**)&xs,  g_xs);
    cudaGetSymbolAddress((void**)&k,   g_k);
    cudaGetSymbolAddress((void**)&v,   g_v);
    cudaGetSymbolAddress((void**)&o,   g_o);

    dim3 ggrid(HW / BN, C_ / BM, B_);     // (8, 6, 2)

    mma_gemm_kernel<<<ggrid, 128>>>(q, Wq, x, bq);

    dim3 obk(64, 4);
    offset_kernel<<<B_ * NGROUP * NS / 4, obk>>>(q, dw_w, dw_b, ln_g, ln_b, pw_w, pos);

    sample_kernel<<<(B_ * NGROUP * GC * NS + 255) / 256, 256>>>(x, pos, xs);

    dim3 kvgrid(HW / BN, 12, B_);         // (8, 12, 2)
    mma_gemm_kv_kernel<<<kvgrid, 128>>>(k, Wk, bk, v, Wv, bv, xs);

    dim3 agrid(HW / 64, B_ * NHEAD);
    attn2_kernel<<<agrid, 256>>>(q, k, v, pos, rpe, o);

    mma_gemm_kernel<<<ggrid, 128>>>(y, Wo, o, bo);
}

// round 6
// speedup vs baseline: 1.9497x; 1.9497x over previous
#include <cuda_runtime.h>
#include <math.h>

#define B_  2
#define C_  384
#define HW  1024
#define NHEAD 12
#define NGROUP 6
#define HC  32
#define GC  64
#define NS  1024
#define SCALE 0.17677669529663687f   // 1/sqrt(32)

// ---------------- scratch ----------------------------------------------------
__device__ float g_q  [B_ * C_ * HW];
__device__ float g_pos[B_ * NGROUP * NS * 2];
__device__ float g_xs [B_ * NGROUP * GC * NS];
__device__ float g_k  [B_ * C_ * NS];
__device__ float g_v  [B_ * C_ * NS];
__device__ float g_o  [B_ * C_ * HW];

// ---------------- tf32 helpers -----------------------------------------------
__device__ __forceinline__ unsigned f2tf32(float f) {
    unsigned r;
    asm("cvt.rna.tf32.f32 %0, %1;" : "=r"(r) : "f"(f));
    return r;
}

__device__ __forceinline__ void mma_tf32(float d[4], const unsigned a[4], unsigned b0, unsigned b1) {
    asm volatile(
        "mma.sync.aligned.m16n8k8.row.col.f32.tf32.tf32.f32 "
        "{%0,%1,%2,%3}, {%4,%5,%6,%7}, {%8,%9}, {%0,%1,%2,%3};"
        : "+f"(d[0]), "+f"(d[1]), "+f"(d[2]), "+f"(d[3])
        : "r"(a[0]), "r"(a[1]), "r"(a[2]), "r"(a[3]), "r"(b0), "r"(b1));
}

// ---------------- tf32 tensor-core projection GEMM ---------------------------
#define BM 64
#define BN 128
#define BK 16
#define APAD 20
#define BPAD 136

__device__ __forceinline__ void mma_gemm_core(
        float* __restrict__ Yb, const float* __restrict__ W,
        const float* __restrict__ bias, const float* __restrict__ Xb,
        int o0, int p0) {
    __shared__ unsigned As[2][BM][APAD];
    __shared__ unsigned Bs[2][BK][BPAD];

    int tid = threadIdx.x;
    int lane = tid & 31, warp = tid >> 5;
    int wm = warp & 1, wn = warp >> 1;
    int qr = lane >> 2, qc = lane & 3;

    float d[2][8][4];
    #pragma unroll
    for (int mt = 0; mt < 2; mt++)
        #pragma unroll
        for (int nt = 0; nt < 8; nt++)
            #pragma unroll
            for (int r = 0; r < 4; r++) d[mt][nt][r] = 0.f;

    float4 ra[2], rb[4];

    int a_row0 = tid >> 2,          a_c4_0 = tid & 3;
    int a_row1 = (tid + 128) >> 2,  a_c4_1 = tid & 3;
    int b_row[4], b_c4[4];
    #pragma unroll
    for (int j = 0; j < 4; j++) { int idx = tid + j * 128; b_row[j] = idx >> 5; b_c4[j] = idx & 31; }

    #define LDG_TILE(k0)                                                                  \
        ra[0] = *(const float4*)&W[(size_t)(o0 + a_row0) * C_ + (k0) + a_c4_0 * 4];       \
        ra[1] = *(const float4*)&W[(size_t)(o0 + a_row1) * C_ + (k0) + a_c4_1 * 4];       \
        _Pragma("unroll")                                                                 \
        for (int j = 0; j < 4; j++)                                                       \
            rb[j] = *(const float4*)&Xb[(size_t)((k0) + b_row[j]) * HW + p0 + b_c4[j] * 4];

    #define STS_TILE(buf)                                                                 \
        As[buf][a_row0][a_c4_0 * 4 + 0] = f2tf32(ra[0].x);                                \
        As[buf][a_row0][a_c4_0 * 4 + 1] = f2tf32(ra[0].y);                                \
        As[buf][a_row0][a_c4_0 * 4 + 2] = f2tf32(ra[0].z);                                \
        As[buf][a_row0][a_c4_0 * 4 + 3] = f2tf32(ra[0].w);                                \
        As[buf][a_row1][a_c4_1 * 4 + 0] = f2tf32(ra[1].x);                                \
        As[buf][a_row1][a_c4_1 * 4 + 1] = f2tf32(ra[1].y);                                \
        As[buf][a_row1][a_c4_1 * 4 + 2] = f2tf32(ra[1].z);                                \
        As[buf][a_row1][a_c4_1 * 4 + 3] = f2tf32(ra[1].w);                                \
        _Pragma("unroll")                                                                 \
        for (int j = 0; j < 4; j++) {                                                     \
            Bs[buf][b_row[j]][b_c4[j] * 4 + 0] = f2tf32(rb[j].x);                         \
            Bs[buf][b_row[j]][b_c4[j] * 4 + 1] = f2tf32(rb[j].y);                         \
            Bs[buf][b_row[j]][b_c4[j] * 4 + 2] = f2tf32(rb[j].z);                         \
            Bs[buf][b_row[j]][b_c4[j] * 4 + 3] = f2tf32(rb[j].w);                         \
        }

    LDG_TILE(0);
    STS_TILE(0);
    __syncthreads();

    const int NIT = C_ / BK;
    for (int it = 0; it < NIT; it++) {
        int cur = it & 1;
        if (it < NIT - 1) { LDG_TILE((it + 1) * BK); }
        #pragma unroll
        for (int ks = 0; ks < 2; ks++) {
            int kb = ks * 8;
            unsigned af[2][4];
            #pragma unroll
            for (int mt = 0; mt < 2; mt++) {
                int rbse = wm * 32 + mt * 16;
                af[mt][0] = As[cur][rbse + qr    ][kb + qc    ];
                af[mt][1] = As[cur][rbse + qr + 8][kb + qc    ];
                af[mt][2] = As[cur][rbse + qr    ][kb + qc + 4];
                af[mt][3] = As[cur][rbse + qr + 8][kb + qc + 4];
            }
            #pragma unroll
            for (int nt = 0; nt < 8; nt++) {
                int nb = wn * 64 + nt * 8 + qr;
                unsigned b0 = Bs[cur][kb + qc    ][nb];
                unsigned b1 = Bs[cur][kb + qc + 4][nb];
                mma_tf32(d[0][nt], af[0], b0, b1);
                mma_tf32(d[1][nt], af[1], b0, b1);
            }
        }
        if (it < NIT - 1) { STS_TILE(cur ^ 1); }
        __syncthreads();
    }

    #pragma unroll
    for (int mt = 0; mt < 2; mt++) {
        int ob = o0 + wm * 32 + mt * 16 + qr;
        float bv0 = bias[ob], bv1 = bias[ob + 8];
        #pragma unroll
        for (int nt = 0; nt < 8; nt++) {
            int p = p0 + wn * 64 + nt * 8 + 2 * qc;
            *(float2*)&Yb[(size_t)ob * HW + p] =
                make_float2(d[mt][nt][0] + bv0, d[mt][nt][1] + bv0);
            *(float2*)&Yb[(size_t)(ob + 8) * HW + p] =
                make_float2(d[mt][nt][2] + bv1, d[mt][nt][3] + bv1);
        }
    }
    #undef LDG_TILE
    #undef STS_TILE
}

__global__ __launch_bounds__(128) void mma_gemm_kernel(
        float* __restrict__ Y, const float* __restrict__ W,
        const float* __restrict__ X, const float* __restrict__ bias) {
    int b = blockIdx.z;
    mma_gemm_core(Y + (size_t)b * C_ * HW, W, bias, X + (size_t)b * C_ * HW,
                  blockIdx.y * BM, blockIdx.x * BN);
}

__global__ __launch_bounds__(128) void mma_gemm_kv_kernel(
        float* __restrict__ K, const float* __restrict__ Wk, const float* __restrict__ bk,
        float* __restrict__ V, const float* __restrict__ Wv, const float* __restrict__ bv,
        const float* __restrict__ X) {
    int b = blockIdx.z;
    int yy = blockIdx.y;
    const float* W  = (yy < 6) ? Wk : Wv;
    const float* bb = (yy < 6) ? bk : bv;
    float* Y        = (yy < 6) ? K  : V;
    mma_gemm_core(Y + (size_t)b * C_ * NS, W, bb, X + (size_t)b * C_ * NS,
                  (yy % 6) * BM, blockIdx.x * BN);
}

// ---------------- offset branch ----------------------------------------------
__global__ void offset_kernel(const float* __restrict__ q,
                              const float* __restrict__ dw_w, const float* __restrict__ dw_b,
                              const float* __restrict__ ln_g, const float* __restrict__ ln_b,
                              const float* __restrict__ pw_w, float* __restrict__ pos) {
    int c = threadIdx.x;
    int p = threadIdx.y;
    int bs = blockIdx.x * 4 + p;
    int bg = bs >> 10;
    int s  = bs & 1023;
    int y = s >> 5, x = s & 31;
    int b = bg / NGROUP, g = bg % NGROUP;
    const float* qc = q + ((size_t)b * C_ + g * GC + c) * HW;
    const float* w  = dw_w + c * 49;
    float acc = dw_b[c];
    #pragma unroll
    for (int dy = 0; dy < 7; dy++) {
        int yy = y + dy - 3;
        if (yy < 0 || yy > 31) continue;
        #pragma unroll
        for (int dx = 0; dx < 7; dx++) {
            int xx = x + dx - 3;
            if (xx < 0 || xx > 31) continue;
            acc += w[dy * 7 + dx] * qc[yy * 32 + xx];
        }
    }
    __shared__ float ra[4][2], rb[4][2], rc[4][2], rd[4][2];
    int half = c >> 5;
    float v = acc;
    #pragma unroll
    for (int o = 16; o; o >>= 1) v += __shfl_down_sync(0xffffffffu, v, o);
    if ((c & 31) == 0) ra[p][half] = v;
    __syncthreads();
    float mu = (ra[p][0] + ra[p][1]) * (1.f / 64.f);
    float d = acc - mu;
    float v2 = d * d;
    #pragma unroll
    for (int o = 16; o; o >>= 1) v2 += __shfl_down_sync(0xffffffffu, v2, o);
    if ((c & 31) == 0) rb[p][half] = v2;
    __syncthreads();
    float var = (rb[p][0] + rb[p][1]) * (1.f / 64.f);
    float on = d * rsqrtf(var + 1e-5f) * ln_g[c] + ln_b[c];
    float ge = 0.5f * on * (1.f + erff(on * 0.70710678118654752f));
    float p0 = ge * pw_w[c];
    float p1 = ge * pw_w[GC + c];
    #pragma unroll
    for (int o = 16; o; o >>= 1) {
        p0 += __shfl_down_sync(0xffffffffu, p0, o);
        p1 += __shfl_down_sync(0xffffffffu, p1, o);
    }
    if ((c & 31) == 0) { rc[p][half] = p0; rd[p][half] = p1; }
    __syncthreads();
    if (c == 0) {
        float off_y = tanhf(rc[p][0] + rc[p][1]) * (2.0f / 32.0f);
        float off_x = tanhf(rd[p][0] + rd[p][1]) * (2.0f / 32.0f);
        float ry = ((float)y + 0.5f) * (1.f / 16.f) - 1.f;
        float rx = ((float)x + 0.5f) * (1.f / 16.f) - 1.f;
        pos[(bg * NS + s) * 2 + 0] = off_y + ry;
        pos[(bg * NS + s) * 2 + 1] = off_x + rx;
    }
}

// ---------------- grid sample -> xs ------------------------------------------
__global__ void sample_kernel(const float* __restrict__ x, const float* __restrict__ pos,
                              float* __restrict__ xs) {
    int idx = blockIdx.x * blockDim.x + threadIdx.x;
    if (idx >= B_ * NGROUP * GC * NS) return;
    int s  = idx & 1023;
    int c  = (idx >> 10) & 63;
    int bg = idx >> 16;
    int b = bg / NGROUP, g = bg % NGROUP;
    float py = pos[(bg * NS + s) * 2 + 0];
    float px = pos[(bg * NS + s) * 2 + 1];
    float gx = (px + 1.f) * 0.5f * 31.f;
    float gy = (py + 1.f) * 0.5f * 31.f;
    float x0f = floorf(gx), y0f = floorf(gy);
    float wx = gx - x0f, wy = gy - y0f;
    int x0 = (int)x0f, y0 = (int)y0f;
    const float* img = x + ((size_t)b * C_ + g * GC + c) * HW;
    float acc = 0.f;
    bool x0v = (unsigned)x0 < 32u, x1v = (unsigned)(x0 + 1) < 32u;
    bool y0v = (unsigned)y0 < 32u, y1v = (unsigned)(y0 + 1) < 32u;
    if (x0v && y0v) acc += (1.f - wx) * (1.f - wy) * img[y0 * 32 + x0];
    if (x1v && y0v) acc += wx * (1.f - wy)         * img[y0 * 32 + x0 + 1];
    if (x0v && y1v) acc += (1.f - wx) * wy         * img[(y0 + 1) * 32 + x0];
    if (x1v && y1v) acc += wx * wy                 * img[(y0 + 1) * 32 + x0 + 1];
    xs[idx] = acc;
}

// ---------------- tensor-core flash attention --------------------------------
// block: 64 queries, 128 threads (4 warps x 16 query rows). dynamic smem layout:
//   tab [63*63]            RPE table for this head (fp32)
//   Qs  [64][33] (tf32)    K-major query tile
//   Ks  [64][33] (tf32)    per-iter key tile     [n][c]
//   Vs  [64][33] (tf32)    per-iter value tile   [n][c]
//   Ps  [64][68] (tf32)    probability tile (warp-private rows)
//   posy[64], posx[64]
#define TAB_W 3969
#define QS_OFF  (TAB_W)
#define KS_OFF  (QS_OFF + 64 * 33)
#define VS_OFF  (KS_OFF + 64 * 33)
#define PS_OFF  (VS_OFF + 64 * 33)
#define PY_OFF  (PS_OFF + 64 * 68)
#define PX_OFF  (PY_OFF + 64)
#define ATTN_SMEM_WORDS (PX_OFF + 64)

__device__ __forceinline__ float bilin_s(const float* __restrict__ tab, float gy, float gx) {
    float x0f = floorf(gx), y0f = floorf(gy);
    float wx = gx - x0f, wy = gy - y0f;
    int x0 = (int)x0f, y0 = (int)y0f;
    bool x0v = (unsigned)x0 < 63u, x1v = (unsigned)(x0 + 1) < 63u;
    bool y0v = (unsigned)y0 < 63u, y1v = (unsigned)(y0 + 1) < 63u;
    float r = 0.f;
    if (x0v && y0v) r += (1.f - wx) * (1.f - wy) * tab[y0 * 63 + x0];
    if (x1v && y0v) r += wx * (1.f - wy)         * tab[y0 * 63 + x0 + 1];
    if (x0v && y1v) r += (1.f - wx) * wy         * tab[(y0 + 1) * 63 + x0];
    if (x1v && y1v) r += wx * wy                 * tab[(y0 + 1) * 63 + x0 + 1];
    return r;
}

__global__ __launch_bounds__(128) void attn3_kernel(
        const float* __restrict__ q, const float* __restrict__ k,
        const float* __restrict__ v, const float* __restrict__ pos,
        const float* __restrict__ rpe, float* __restrict__ out) {
    extern __shared__ unsigned smem_u[];
    float*    tab  = (float*)smem_u;
    unsigned* Qs   = smem_u + QS_OFF;
    unsigned* Ks   = smem_u + KS_OFF;
    unsigned* Vs   = smem_u + VS_OFF;
    unsigned* Ps   = smem_u + PS_OFF;
    float*    posy = (float*)(smem_u + PY_OFF);
    float*    posx = (float*)(smem_u + PX_OFF);

    int bh = blockIdx.y;
    int b = bh / NHEAD, h = bh % NHEAD;
    int bg = b * NGROUP + (h >> 1);
    int m0 = blockIdx.x * 64;
    int tid = threadIdx.x;
    int lane = tid & 31, warp = tid >> 5;
    int qr = lane >> 2, qc = lane & 3;

    const float* qb = q + ((size_t)b * C_ + h * HC) * HW;
    const float* kb = k + ((size_t)b * C_ + h * HC) * NS;
    const float* vb = v + ((size_t)b * C_ + h * HC) * NS;
    const float* tg = rpe + h * 63 * 63;

    // stage RPE table + Q (once)
    for (int i = tid; i < TAB_W; i += 128) tab[i] = tg[i];
    for (int i = tid; i < 64 * 32; i += 128) {
        int c = i >> 6, m = i & 63;
        Qs[m * 33 + c] = f2tf32(qb[(size_t)c * HW + m0 + m]);
    }
    __syncthreads();

    // Q fragments: warp owns rows warp*16 .. +15
    unsigned af[4][4];
    int r0 = warp * 16 + qr;
    #pragma unroll
    for (int kc = 0; kc < 4; kc++) {
        af[kc][0] = Qs[(r0    ) * 33 + kc * 8 + qc    ];
        af[kc][1] = Qs[(r0 + 8) * 33 + kc * 8 + qc    ];
        af[kc][2] = Qs[(r0    ) * 33 + kc * 8 + qc + 4];
        af[kc][3] = Qs[(r0 + 8) * 33 + kc * 8 + qc + 4];
    }

    // query coords of this thread's two rows
    int mA = m0 + r0, mB = mA + 8;
    float qyA = ((float)(mA >> 5) + 0.5f) * (1.f / 16.f) - 1.f;
    float qxA = ((float)(mA & 31) + 0.5f) * (1.f / 16.f) - 1.f;
    float qyB = ((float)(mB >> 5) + 0.5f) * (1.f / 16.f) - 1.f;
    float qxB = ((float)(mB & 31) + 0.5f) * (1.f / 16.f) - 1.f;

    float mrA = -1e30f, mrB = -1e30f, lrA = 0.f, lrB = 0.f;
    float O[4][4] = {};    // 4 channel tiles x (c0..c3)

    for (int n0 = 0; n0 < NS; n0 += 64) {
        __syncthreads();
        for (int i = tid; i < 64 * 32; i += 128) {
            int c = i >> 6, n = i & 63;
            Ks[n * 33 + c] = f2tf32(kb[(size_t)c * NS + n0 + n]);
            Vs[n * 33 + c] = f2tf32(vb[(size_t)c * NS + n0 + n]);
        }
        if (tid < 64) {
            posy[tid] = pos[(bg * NS + n0 + tid) * 2 + 0];
            posx[tid] = pos[(bg * NS + n0 + tid) * 2 + 1];
        }
        __syncthreads();

        // ---- S = Q K^T via mma ----
        float s[8][4];
        #pragma unroll
        for (int ct = 0; ct < 8; ct++) { s[ct][0] = s[ct][1] = s[ct][2] = s[ct][3] = 0.f; }
        #pragma unroll
        for (int ct = 0; ct < 8; ct++) {
            #pragma unroll
            for (int kc = 0; kc < 4; kc++) {
                unsigned b0 = Ks[(ct * 8 + qr) * 33 + kc * 8 + qc    ];
                unsigned b1 = Ks[(ct * 8 + qr) * 33 + kc * 8 + qc + 4];
                mma_tf32(s[ct], af[kc], b0, b1);
            }
        }

        // ---- scale + RPE bias ----
        #pragma unroll
        for (int ct = 0; ct < 8; ct++) {
            #pragma unroll
            for (int j = 0; j < 2; j++) {
                int nl = ct * 8 + 2 * qc + j;
                float py = posy[nl], px = posx[nl];
                float gyA = ((qyA - py) * 0.5f + 1.f) * 31.f;
                float gxA = ((qxA - px) * 0.5f + 1.f) * 31.f;
                float gyB = ((qyB - py) * 0.5f + 1.f) * 31.f;
                float gxB = ((qxB - px) * 0.5f + 1.f) * 31.f;
                s[ct][j]     = s[ct][j]     * SCALE + bilin_s(tab, gyA, gxA);
                s[ct][2 + j] = s[ct][2 + j] * SCALE + bilin_s(tab, gyB, gxB);
            }
        }

        // ---- online softmax (rows A=qr, B=qr+8 of this warp) ----
        float tmA = -1e30f, tmB = -1e30f;
        #pragma unroll
        for (int ct = 0; ct < 8; ct++) {
            tmA = fmaxf(tmA, fmaxf(s[ct][0], s[ct][1]));
            tmB = fmaxf(tmB, fmaxf(s[ct][2], s[ct][3]));
        }
        tmA = fmaxf(tmA, __shfl_xor_sync(0xffffffffu, tmA, 1));
        tmA = fmaxf(tmA, __shfl_xor_sync(0xffffffffu, tmA, 2));
        tmB = fmaxf(tmB, __shfl_xor_sync(0xffffffffu, tmB, 1));
        tmB = fmaxf(tmB, __shfl_xor_sync(0xffffffffu, tmB, 2));
        float mnA = fmaxf(mrA, tmA), mnB = fmaxf(mrB, tmB);
        float aA = __expf(mrA - mnA), aB = __expf(mrB - mnB);
        mrA = mnA; mrB = mnB;

        float rsA = 0.f, rsB = 0.f;
        #pragma unroll
        for (int ct = 0; ct < 8; ct++) {
            s[ct][0] = __expf(s[ct][0] - mnA);
            s[ct][1] = __expf(s[ct][1] - mnA);
            s[ct][2] = __expf(s[ct][2] - mnB);
            s[ct][3] = __expf(s[ct][3] - mnB);
            rsA += s[ct][0] + s[ct][1];
            rsB += s[ct][2] + s[ct][3];
            Ps[(r0    ) * 68 + ct * 8 + 2 * qc    ] = f2tf32(s[ct][0]);
            Ps[(r0    ) * 68 + ct * 8 + 2 * qc + 1] = f2tf32(s[ct][1]);
            Ps[(r0 + 8) * 68 + ct * 8 + 2 * qc    ] = f2tf32(s[ct][2]);
            Ps[(r0 + 8) * 68 + ct * 8 + 2 * qc + 1] = f2tf32(s[ct][3]);
        }
        rsA += __shfl_xor_sync(0xffffffffu, rsA, 1);
        rsA += __shfl_xor_sync(0xffffffffu, rsA, 2);
        rsB += __shfl_xor_sync(0xffffffffu, rsB, 1);
        rsB += __shfl_xor_sync(0xffffffffu, rsB, 2);
        lrA = lrA * aA + rsA;
        lrB = lrB * aB + rsB;
        #pragma unroll
        for (int ct = 0; ct < 4; ct++) {
            O[ct][0] *= aA; O[ct][1] *= aA;
            O[ct][2] *= aB; O[ct][3] *= aB;
        }
        __syncwarp();

        // ---- O += P V (P rows warp-private) ----
        #pragma unroll
        for (int kc = 0; kc < 8; kc++) {
            unsigned pa[4];
            pa[0] = Ps[(r0    ) * 68 + kc * 8 + qc    ];
            pa[1] = Ps[(r0 + 8) * 68 + kc * 8 + qc    ];
            pa[2] = Ps[(r0    ) * 68 + kc * 8 + qc + 4];
            pa[3] = Ps[(r0 + 8) * 68 + kc * 8 + qc + 4];
            #pragma unroll
            for (int ct = 0; ct < 4; ct++) {
                unsigned b0 = Vs[(kc * 8 + qc    ) * 33 + ct * 8 + qr];
                unsigned b1 = Vs[(kc * 8 + qc + 4) * 33 + ct * 8 + qr];
                mma_tf32(O[ct], pa, b0, b1);
            }
        }
        __syncwarp();
    }

    // ---- write out: out[c][m] ----
    float invA = 1.f / lrA, invB = 1.f / lrB;
    float* ob = out + ((size_t)b * C_ + h * HC) * HW;
    #pragma unroll
    for (int ct = 0; ct < 4; ct++) {
        int c0 = ct * 8 + 2 * qc, c1 = c0 + 1;
        ob[(size_t)c0 * HW + m0 + r0    ] = O[ct][0] * invA;
        ob[(size_t)c1 * HW + m0 + r0    ] = O[ct][1] * invA;
        ob[(size_t)c0 * HW + m0 + r0 + 8] = O[ct][2] * invB;
        ob[(size_t)c1 * HW + m0 + r0 + 8] = O[ct][3] * invB;
    }
}

// ---------------- launch -----------------------------------------------------
extern "C" void kernel_launch(void* const* d_in, const int* in_sizes, int n_in,
                              void* d_out, int out_size) {
    const float* x      = (const float*)d_in[0];
    const float* Wq     = (const float*)d_in[1];
    const float* bq     = (const float*)d_in[2];
    const float* Wk     = (const float*)d_in[3];
    const float* bk     = (const float*)d_in[4];
    const float* Wv     = (const float*)d_in[5];
    const float* bv     = (const float*)d_in[6];
    const float* Wo     = (const float*)d_in[7];
    const float* bo     = (const float*)d_in[8];
    const float* dw_w   = (const float*)d_in[9];
    const float* dw_b   = (const float*)d_in[10];
    const float* ln_g   = (const float*)d_in[11];
    const float* ln_b   = (const float*)d_in[12];
    const float* pw_w   = (const float*)d_in[13];
    const float* rpe    = (const float*)d_in[14];
    float* y = (float*)d_out;

    float *q, *pos, *xs, *k, *v, *o;
    cudaGetSymbolAddress((void**)&q,   g_q);
    cudaGetSymbolAddress((void**)&pos, g_pos);
    cudaGetSymbolAddress((void**)&xs,  g_xs);
    cudaGetSymbolAddress((void**)&k,   g_k);
    cudaGetSymbolAddress((void**)&v,   g_v);
    cudaGetSymbolAddress((void**)&o,   g_o);

    static int smem_set = 0;
    if (!smem_set) {
        cudaFuncSetAttribute(attn3_kernel, cudaFuncAttributeMaxDynamicSharedMemorySize,
                             ATTN_SMEM_WORDS * 4);
        smem_set = 1;
    }

    dim3 ggrid(HW / BN, C_ / BM, B_);

    mma_gemm_kernel<<<ggrid, 128>>>(q, Wq, x, bq);

    dim3 obk(64, 4);
    offset_kernel<<<B_ * NGROUP * NS / 4, obk>>>(q, dw_w, dw_b, ln_g, ln_b, pw_w, pos);

    sample_kernel<<<(B_ * NGROUP * GC * NS + 255) / 256, 256>>>(x, pos, xs);

    dim3 kvgrid(HW / BN, 12, B_);
    mma_gemm_kv_kernel<<<kvgrid, 128>>>(k, Wk, bk, v, Wv, bv, xs);

    dim3 agrid(HW / 64, B_ * NHEAD);
    attn3_kernel<<<agrid, 128, ATTN_SMEM_WORDS * 4>>>(q, k, v, pos, rpe, o);

    mma_gemm_kernel<<<ggrid, 128>>>(y, Wo, o, bo);
}